// round 1
// baseline (speedup 1.0000x reference)
#include <cuda_runtime.h>
#include <math.h>
#include <stdint.h>

// ---------------- problem constants ----------------
#define NB 4
#define SS 1024
#define DD 1536
#define NH 12
#define HDIM 128
#define MAXC 256
#define SM1 1023                 // S-1
#define ROWS_DET (NB*SM1)        // 4092
#define CS_TOT (1023+511+255)    // 1789

// ---------------- scratch (device globals; no allocation) ----------------
__device__ float g_xling[(size_t)NB*SS*DD];
__device__ float g_norm[NB*SS];
__device__ float g_cs[NB*CS_TOT];
__device__ float g_base[NB*SM1];
__device__ float g_bi[(size_t)ROWS_DET*2*DD];
__device__ float g_h1[(size_t)3*ROWS_DET*DD];
__device__ float g_h2[(size_t)3*ROWS_DET*(DD/2)];
__device__ float g_final[NB*SM1];
__device__ int   g_seg[NB*SS];
__device__ int   g_segstart[NB*MAXC];
__device__ int   g_segcount[NB*MAXC];
__device__ float g_qkv[(size_t)NB*SS*3*DD];
__device__ float g_scores[(size_t)NB*NH*SS*SS];
__device__ float g_ctx[(size_t)NB*SS*DD];
__device__ float g_attnout[(size_t)NB*SS*DD];
__device__ float g_chunk[(size_t)NB*MAXC*DD];
__device__ float g_hproc[(size_t)NB*MAXC*2*DD];
__device__ float g_y[(size_t)NB*MAXC*DD];

// ---------------- helpers ----------------
__device__ __forceinline__ float gelu_exact(float v) {
    return 0.5f * v * (1.0f + erff(v * 0.70710678118654752440f));
}

// ---------------- generic tiled SGEMM ----------------
// C[m,n] = sum_k A[m,k] * (BT ? B[n,k] : B[k,n]) (+ bias[n]) (+ gelu)
// Batched: per-z offsets  off = (z%innerN)*sXi + (z/innerN)*sXo
#define BM 128
#define BN 128
#define BKK 16
#define TM 8
#define TN 8

template<int ACT, bool BT>
__global__ __launch_bounds__(256)
void gemm_k(const float* __restrict__ A, const float* __restrict__ B,
            const float* __restrict__ bias, float* __restrict__ C,
            int M, int N, int K, int lda, int ldb, int ldc,
            long long sAi, long long sAo, long long sBi, long long sBo,
            long long sCi, long long sCo, long long sbias, int innerN)
{
    int z = blockIdx.z;
    int zi = z % innerN, zo = z / innerN;
    A += (size_t)(zi*sAi + zo*sAo);
    B += (size_t)(zi*sBi + zo*sBo);
    C += (size_t)(zi*sCi + zo*sCo);
    if (bias) bias += (size_t)z * (size_t)sbias;

    __shared__ float As[BKK][BM+4];
    __shared__ float Bs[BKK][BN+4];

    int tid = threadIdx.x;
    int tr = tid >> 4;       // 0..15
    int tc = tid & 15;       // 0..15
    int m0 = blockIdx.y * BM;
    int n0 = blockIdx.x * BN;

    float acc[TM][TN];
    #pragma unroll
    for (int i = 0; i < TM; i++)
        #pragma unroll
        for (int j = 0; j < TN; j++) acc[i][j] = 0.f;

    for (int k0 = 0; k0 < K; k0 += BKK) {
        // A tile: 128x16 = 512 float4, 2 per thread; store transposed
        #pragma unroll
        for (int l = 0; l < 2; l++) {
            int f = tid + l*256;
            int row = f >> 2;
            int kk  = (f & 3) * 4;
            float4 v = make_float4(0.f,0.f,0.f,0.f);
            if (m0 + row < M)
                v = *(const float4*)(A + (long long)(m0+row)*lda + k0 + kk);
            As[kk+0][row]=v.x; As[kk+1][row]=v.y; As[kk+2][row]=v.z; As[kk+3][row]=v.w;
        }
        if (BT) {
            #pragma unroll
            for (int l = 0; l < 2; l++) {
                int f = tid + l*256;
                int row = f >> 2;     // n index
                int kk  = (f & 3)*4;
                float4 v = make_float4(0.f,0.f,0.f,0.f);
                if (n0 + row < N)
                    v = *(const float4*)(B + (long long)(n0+row)*ldb + k0 + kk);
                Bs[kk+0][row]=v.x; Bs[kk+1][row]=v.y; Bs[kk+2][row]=v.z; Bs[kk+3][row]=v.w;
            }
        } else {
            #pragma unroll
            for (int l = 0; l < 2; l++) {
                int f = tid + l*256;
                int kk  = f >> 5;            // 0..15
                int col = (f & 31)*4;
                float4 v = make_float4(0.f,0.f,0.f,0.f);
                if (n0 + col < N)
                    v = *(const float4*)(B + (long long)(k0+kk)*ldb + n0 + col);
                Bs[kk][col]=v.x; Bs[kk][col+1]=v.y; Bs[kk][col+2]=v.z; Bs[kk][col+3]=v.w;
            }
        }
        __syncthreads();

        #pragma unroll
        for (int k = 0; k < BKK; k++) {
            float a[TM], b[TN];
            #pragma unroll
            for (int i = 0; i < TM; i++) a[i] = As[k][tr*TM + i];
            #pragma unroll
            for (int j = 0; j < TN; j++) b[j] = Bs[k][tc*TN + j];
            #pragma unroll
            for (int i = 0; i < TM; i++)
                #pragma unroll
                for (int j = 0; j < TN; j++)
                    acc[i][j] += a[i] * b[j];
        }
        __syncthreads();
    }

    #pragma unroll
    for (int i = 0; i < TM; i++) {
        int m = m0 + tr*TM + i;
        if (m >= M) continue;
        #pragma unroll
        for (int j = 0; j < TN; j++) {
            int n = n0 + tc*TN + j;
            if (n >= N) continue;
            float v = acc[i][j];
            if (bias) v += bias[n];
            if (ACT == 1) v = gelu_exact(v);
            C[(long long)m*ldc + n] = v;
        }
    }
}

// ---------------- row norms of x_ling ----------------
__global__ void norm_k() {
    int r = blockIdx.x;                 // 0..4095
    const float* p = g_xling + (size_t)r * DD;
    float ss = 0.f;
    for (int i = threadIdx.x; i < DD; i += 256) { float v = p[i]; ss += v*v; }
    __shared__ float sh[256];
    sh[threadIdx.x] = ss; __syncthreads();
    for (int o = 128; o > 0; o >>= 1) {
        if (threadIdx.x < o) sh[threadIdx.x] += sh[threadIdx.x + o];
        __syncthreads();
    }
    if (threadIdx.x == 0) g_norm[r] = fmaxf(sqrtf(sh[0]), 1e-8f);
}

// ---------------- cosine sims at 3 scales ----------------
__global__ void cos_k() {
    int b = blockIdx.y;
    int t = blockIdx.x;                 // 0..1788
    int scale, i;
    if (t < 1023)      { scale = 1; i = t; }
    else if (t < 1534) { scale = 2; i = t - 1023; }
    else               { scale = 4; i = t - 1534; }
    int s0 = i * scale, s1 = s0 + scale;
    const float* a = g_xling + ((size_t)b*SS + s0) * DD;
    const float* c = g_xling + ((size_t)b*SS + s1) * DD;
    float d = 0.f;
    for (int j = threadIdx.x; j < DD; j += 256) d += a[j] * c[j];
    __shared__ float sh[256];
    sh[threadIdx.x] = d; __syncthreads();
    for (int o = 128; o > 0; o >>= 1) {
        if (threadIdx.x < o) sh[threadIdx.x] += sh[threadIdx.x + o];
        __syncthreads();
    }
    if (threadIdx.x == 0)
        g_cs[b*CS_TOT + t] = sh[0] / (g_norm[b*SS + s0] * g_norm[b*SS + s1]);
}

// ---------------- interp + base ----------------
__global__ void base_k() {
    int idx = blockIdx.x * 256 + threadIdx.x;
    if (idx >= NB*SM1) return;
    int b = idx / SM1, j = idx % SM1;
    const int   Ls[3]   = {1023, 511, 255};
    const int   offs[3] = {0, 1023, 1534};
    float acc = 0.f;
    #pragma unroll
    for (int u = 0; u < 3; u++) {
        int L = Ls[u];
        float ratio = (float)((double)L / 1023.0);
        float src = ((float)j + 0.5f) * ratio - 0.5f;
        src = fminf(fmaxf(src, 0.0f), (float)(L - 1));
        int i0 = (int)floorf(src);
        int i1 = min(i0 + 1, L - 1);
        float w = src - (float)i0;
        const float* cs = g_cs + b*CS_TOT + offs[u];
        acc += cs[i0] * (1.0f - w) + cs[i1] * w;
    }
    float avg = acc / 3.0f;
    g_base[idx] = 0.5f * (1.0f - avg);
}

// ---------------- bigram build: bi = [x[:,:-1], x[:,1:]] ----------------
__global__ void bi_k(const float* __restrict__ x) {
    long long idx4 = (long long)blockIdx.x * 256 + threadIdx.x;
    const long long total4 = (long long)ROWS_DET * (2*DD) / 4;
    if (idx4 >= total4) return;
    int row = (int)(idx4 / (2*DD/4));
    int k = (int)(idx4 % (2*DD/4)) * 4;
    int b = row / SM1, s = row % SM1;
    const float* src = (k < DD)
        ? x + ((size_t)b*SS + s    ) * DD + k
        : x + ((size_t)b*SS + s + 1) * DD + (k - DD);
    *(float4*)(g_bi + (size_t)row*(2*DD) + k) = *(const float4*)src;
}

// ---------------- learned sigmoid head + final boundary score ----------------
__global__ void learned_final_k(const float* __restrict__ detW3,
                                const float* __restrict__ detb3) {
    int r = blockIdx.x;                 // 0..4091
    __shared__ float sh[256];
    __shared__ float sacc;
    if (threadIdx.x == 0) sacc = 0.f;
    for (int n = 0; n < 3; n++) {
        const float* h2p = g_h2 + ((size_t)n*ROWS_DET + r) * (DD/2);
        const float* w   = detW3 + n*(DD/2);
        float part = 0.f;
        for (int j = threadIdx.x; j < DD/2; j += 256) part += h2p[j] * w[j];
        __syncthreads();
        sh[threadIdx.x] = part; __syncthreads();
        for (int o = 128; o > 0; o >>= 1) {
            if (threadIdx.x < o) sh[threadIdx.x] += sh[threadIdx.x + o];
            __syncthreads();
        }
        if (threadIdx.x == 0) {
            float t = sh[0] + detb3[n];
            sacc += 1.0f / (1.0f + expf(-t));
        }
        __syncthreads();
    }
    if (threadIdx.x == 0)
        g_final[r] = 0.6f * g_base[r] + 0.4f * (sacc / 3.0f);
}

// ---------------- segmentation (serial cumsum per batch) ----------------
__global__ void seg_k() {
    int b = threadIdx.x;
    if (b >= NB) return;
    int cum = 0;
    for (int s = 0; s < SS; s++) {
        float bv = (s == 0) ? 1.0f : g_final[b*SM1 + s - 1];
        cum += (bv > 0.5f) ? 1 : 0;
        g_seg[b*SS + s] = cum - 1;
    }
    for (int m = 0; m < MAXC; m++) { g_segcount[b*MAXC+m] = 0; g_segstart[b*MAXC+m] = 0; }
    for (int s = 0; s < SS; s++) {
        int m = g_seg[b*SS + s];
        if (m < MAXC) {
            if (g_segcount[b*MAXC+m] == 0) g_segstart[b*MAXC+m] = s;
            g_segcount[b*MAXC+m]++;
        }
    }
}

// ---------------- masked row softmax (in place on g_scores) ----------------
__global__ void softmax_k() {
    int z = blockIdx.y;                 // 0..47 (b*12+h)
    int b = z / NH;
    int q = blockIdx.x;
    float* row = g_scores + (size_t)z*SS*SS + (size_t)q*SS;
    int sq = g_seg[b*SS + q];
    const float scale = 1.0f / sqrtf(128.0f);
    __shared__ float sh[256];
    float mx = -3.402823e38f;
    for (int k = threadIdx.x; k < SS; k += 256) {
        float v = (g_seg[b*SS + k] == sq) ? row[k]*scale : -1e9f;
        mx = fmaxf(mx, v);
    }
    sh[threadIdx.x] = mx; __syncthreads();
    for (int o = 128; o > 0; o >>= 1) {
        if (threadIdx.x < o) sh[threadIdx.x] = fmaxf(sh[threadIdx.x], sh[threadIdx.x+o]);
        __syncthreads();
    }
    mx = sh[0]; __syncthreads();
    float sum = 0.f;
    for (int k = threadIdx.x; k < SS; k += 256) {
        float v = (g_seg[b*SS + k] == sq) ? row[k]*scale : -1e9f;
        float e = expf(v - mx);
        row[k] = e;
        sum += e;
    }
    sh[threadIdx.x] = sum; __syncthreads();
    for (int o = 128; o > 0; o >>= 1) {
        if (threadIdx.x < o) sh[threadIdx.x] += sh[threadIdx.x+o];
        __syncthreads();
    }
    float inv = 1.0f / sh[0];
    for (int k = threadIdx.x; k < SS; k += 256) row[k] *= inv;
}

// ---------------- segment pooling + size/pos embeddings ----------------
__global__ void chunk_k(const float* __restrict__ size_emb,
                        const float* __restrict__ pos_enc) {
    int m = blockIdx.x, b = blockIdx.y;
    int cnt = g_segcount[b*MAXC + m];
    int st  = g_segstart[b*MAXC + m];
    for (int d = threadIdx.x; d < DD; d += 256) {
        float v;
        if (cnt > 0) {
            float sum = 0.f;
            for (int s = st; s < st + cnt; s++)
                sum += g_attnout[((size_t)b*SS + s)*DD + d];
            int cl = min(cnt, 1023);
            v = sum / (float)cnt + size_emb[(size_t)cl*DD + d];
        } else v = 0.f;
        v += pos_enc[(size_t)m*DD + d];
        g_chunk[((size_t)b*MAXC + m)*DD + d] = v;
    }
}

// ---------------- final layernorm -> d_out ----------------
__global__ void ln_k(const float* __restrict__ gamma,
                     const float* __restrict__ beta,
                     float* __restrict__ out) {
    int r = blockIdx.x;                 // 0..1023
    const float* y = g_y + (size_t)r*DD;
    __shared__ float sh[256];
    float s = 0.f;
    for (int d = threadIdx.x; d < DD; d += 256) s += y[d];
    sh[threadIdx.x] = s; __syncthreads();
    for (int o = 128; o > 0; o >>= 1) {
        if (threadIdx.x < o) sh[threadIdx.x] += sh[threadIdx.x+o];
        __syncthreads();
    }
    float mu = sh[0] / (float)DD; __syncthreads();
    float v2 = 0.f;
    for (int d = threadIdx.x; d < DD; d += 256) {
        float t = y[d] - mu; v2 += t*t;
    }
    sh[threadIdx.x] = v2; __syncthreads();
    for (int o = 128; o > 0; o >>= 1) {
        if (threadIdx.x < o) sh[threadIdx.x] += sh[threadIdx.x+o];
        __syncthreads();
    }
    float var = sh[0] / (float)DD;
    float inv = 1.0f / sqrtf(var + 1e-5f);
    for (int d = threadIdx.x; d < DD; d += 256)
        out[(size_t)r*DD + d] = (y[d] - mu) * inv * gamma[d] + beta[d];
}

// ---------------- host-side GEMM launcher ----------------
static void gemm(const float* A, const float* B, const float* bias, float* C,
                 int M, int N, int K, int lda, int ldb, int ldc,
                 int act, bool bt,
                 long long sAi, long long sAo, long long sBi, long long sBo,
                 long long sCi, long long sCo, long long sbias,
                 int innerN, int batch)
{
    dim3 grid((N + BN - 1)/BN, (M + BM - 1)/BM, batch);
    dim3 block(256);
    if (bt) {
        if (act == 1) gemm_k<1,true><<<grid,block>>>(A,B,bias,C,M,N,K,lda,ldb,ldc,sAi,sAo,sBi,sBo,sCi,sCo,sbias,innerN);
        else          gemm_k<0,true><<<grid,block>>>(A,B,bias,C,M,N,K,lda,ldb,ldc,sAi,sAo,sBi,sBo,sCi,sCo,sbias,innerN);
    } else {
        if (act == 1) gemm_k<1,false><<<grid,block>>>(A,B,bias,C,M,N,K,lda,ldb,ldc,sAi,sAo,sBi,sBo,sCi,sCo,sbias,innerN);
        else          gemm_k<0,false><<<grid,block>>>(A,B,bias,C,M,N,K,lda,ldb,ldc,sAi,sAo,sBi,sBo,sCi,sCo,sbias,innerN);
    }
}

extern "C" void kernel_launch(void* const* d_in, const int* in_sizes, int n_in,
                              void* d_out, int out_size) {
    const float* x         = (const float*)d_in[0];
    const float* Wp        = (const float*)d_in[1];
    const float* bp        = (const float*)d_in[2];
    const float* detW1     = (const float*)d_in[3];
    const float* detb1     = (const float*)d_in[4];
    const float* detW2     = (const float*)d_in[5];
    const float* detb2     = (const float*)d_in[6];
    const float* detW3     = (const float*)d_in[7];
    const float* detb3     = (const float*)d_in[8];
    const float* in_proj_w = (const float*)d_in[9];
    const float* in_proj_b = (const float*)d_in[10];
    const float* out_w     = (const float*)d_in[11];
    const float* out_b     = (const float*)d_in[12];
    const float* size_emb  = (const float*)d_in[13];
    const float* pos_enc   = (const float*)d_in[14];
    const float* procW1    = (const float*)d_in[15];
    const float* procb1    = (const float*)d_in[16];
    const float* procW2    = (const float*)d_in[17];
    const float* procb2    = (const float*)d_in[18];
    const float* ln_g      = (const float*)d_in[19];
    const float* ln_b      = (const float*)d_in[20];
    float* outp = (float*)d_out;

    void *p;
    cudaGetSymbolAddress(&p, g_xling);   float* xling   = (float*)p;
    cudaGetSymbolAddress(&p, g_bi);      float* bi      = (float*)p;
    cudaGetSymbolAddress(&p, g_h1);      float* h1      = (float*)p;
    cudaGetSymbolAddress(&p, g_h2);      float* h2      = (float*)p;
    cudaGetSymbolAddress(&p, g_qkv);     float* qkv     = (float*)p;
    cudaGetSymbolAddress(&p, g_scores);  float* scores  = (float*)p;
    cudaGetSymbolAddress(&p, g_ctx);     float* ctx     = (float*)p;
    cudaGetSymbolAddress(&p, g_attnout); float* attnout = (float*)p;
    cudaGetSymbolAddress(&p, g_chunk);   float* chunk   = (float*)p;
    cudaGetSymbolAddress(&p, g_hproc);   float* hproc   = (float*)p;
    cudaGetSymbolAddress(&p, g_y);       float* yb      = (float*)p;

    // 1) x_ling = x @ Wp^T + bp
    gemm(x, Wp, bp, xling, NB*SS, DD, DD, DD, DD, DD, 0, true,
         0,0,0,0,0,0,0, 1, 1);

    // 2) row norms
    norm_k<<<NB*SS, 256>>>();

    // 3) cosine sims (3 scales)
    cos_k<<<dim3(CS_TOT, NB), 256>>>();

    // 4) interp + base
    base_k<<<(NB*SM1 + 255)/256, 256>>>();

    // 5) bigram features
    {
        long long total4 = (long long)ROWS_DET * (2*DD) / 4;
        bi_k<<<(unsigned)((total4 + 255)/256), 256>>>(x);
    }

    // 6) h1 = gelu(bi @ detW1[n]^T + detb1[n])   batched over n=3
    gemm(bi, detW1, detb1, h1, ROWS_DET, DD, 2*DD, 2*DD, 2*DD, DD, 1, true,
         0, 0, (long long)DD*2*DD, 0, (long long)ROWS_DET*DD, 0, DD, 3, 3);

    // 7) h2 = gelu(h1 @ detW2[n]^T + detb2[n])   batched over n=3
    gemm(h1, detW2, detb2, h2, ROWS_DET, DD/2, DD, DD, DD, DD/2, 1, true,
         (long long)ROWS_DET*DD, 0, (long long)(DD/2)*DD, 0,
         (long long)ROWS_DET*(DD/2), 0, DD/2, 3, 3);

    // 8) learned head + final boundary scores
    learned_final_k<<<ROWS_DET, 256>>>(detW3, detb3);

    // 9) segmentation
    seg_k<<<1, NB>>>();

    // 10) qkv = x @ in_proj_w^T + in_proj_b
    gemm(x, in_proj_w, in_proj_b, qkv, NB*SS, 3*DD, DD, DD, DD, 3*DD, 0, true,
         0,0,0,0,0,0,0, 1, 1);

    // 11) scores[z] = q_z @ k_z^T   (z = b*12+h, 48 batches)
    gemm(qkv, qkv + DD, nullptr, scores, SS, SS, HDIM,
         3*DD, 3*DD, SS, 0, true,
         HDIM, (long long)SS*3*DD,             // A: inner=h, outer=b
         HDIM, (long long)SS*3*DD,             // B (k) same layout
         (long long)SS*SS, (long long)NH*SS*SS, // C
         0, NH, NB*NH);

    // 12) masked softmax (applies 1/sqrt(HD) + segment mask)
    softmax_k<<<dim3(SS, NB*NH), 256>>>();

    // 13) ctx[z] = attn_z @ v_z   (NN, 48 batches)
    gemm(scores, qkv + 2*DD, nullptr, ctx, SS, HDIM, SS,
         SS, 3*DD, DD, 0, false,
         (long long)SS*SS, (long long)NH*SS*SS,   // A (attn)
         HDIM, (long long)SS*3*DD,                // B (v)
         HDIM, (long long)SS*DD,                  // C (ctx)
         0, NH, NB*NH);

    // 14) attn_out = ctx @ out_w^T + out_b
    gemm(ctx, out_w, out_b, attnout, NB*SS, DD, DD, DD, DD, DD, 0, true,
         0,0,0,0,0,0,0, 1, 1);

    // 15) segment pooling + size/pos embeddings
    chunk_k<<<dim3(MAXC, NB), 256>>>(size_emb, pos_enc);

    // 16) h = gelu(chunk @ procW1^T + procb1)
    gemm(chunk, procW1, procb1, hproc, NB*MAXC, 2*DD, DD, DD, DD, 2*DD, 1, true,
         0,0,0,0,0,0,0, 1, 1);

    // 17) y = h @ procW2^T + procb2
    gemm(hproc, procW2, procb2, yb, NB*MAXC, DD, 2*DD, 2*DD, 2*DD, DD, 0, true,
         0,0,0,0,0,0,0, 1, 1);

    // 18) layernorm -> d_out
    ln_k<<<NB*MAXC, 256>>>(ln_g, ln_b, outp);
}

// round 3
// speedup vs baseline: 1.6316x; 1.6316x over previous
#include <cuda_runtime.h>
#include <cuda_bf16.h>
#include <math.h>
#include <stdint.h>

// ---------------- problem constants ----------------
#define NB 4
#define SS 1024
#define DD 1536
#define NH 12
#define HDIM 128
#define MAXC 256
#define SM1 1023
#define ROWS_DET (NB*SM1)        // 4092
#define CS_TOT (1023+511+255)    // 1789

// ---------------- fp32 scratch ----------------
__device__ float g_xling[(size_t)NB*SS*DD];
__device__ float g_norm[NB*SS];
__device__ float g_cs[NB*CS_TOT];
__device__ float g_base[NB*SM1];
__device__ float g_h1[(size_t)3*ROWS_DET*DD];
__device__ float g_h2[(size_t)3*ROWS_DET*(DD/2)];
__device__ float g_final[NB*SM1];
__device__ int   g_seg[NB*SS];
__device__ int   g_segstart[NB*MAXC];
__device__ int   g_segcount[NB*MAXC];
__device__ float g_qkv[(size_t)NB*SS*3*DD];
__device__ float g_scores[(size_t)NB*NH*SS*SS];
__device__ float g_ctx[(size_t)NB*SS*DD];
__device__ float g_attnout[(size_t)NB*SS*DD];
__device__ float g_chunk[(size_t)NB*MAXC*DD];
__device__ float g_hproc[(size_t)NB*MAXC*2*DD];
__device__ float g_y[(size_t)NB*MAXC*DD];

// ---------------- bf16 3-way split scratch [rows][3K] ----------------
__device__ __nv_bfloat16 g_x3[(size_t)NB*SS*3*DD];
__device__ __nv_bfloat16 g_Wp3[(size_t)DD*3*DD];
__device__ __nv_bfloat16 g_bi3[(size_t)ROWS_DET*3*(2*DD)];
__device__ __nv_bfloat16 g_detW1_3[(size_t)3*DD*3*(2*DD)];
__device__ __nv_bfloat16 g_h1_3[(size_t)3*ROWS_DET*3*DD];
__device__ __nv_bfloat16 g_detW2_3[(size_t)3*(DD/2)*3*DD];
__device__ __nv_bfloat16 g_wqkv3[(size_t)3*DD*3*DD];
__device__ __nv_bfloat16 g_ctx3[(size_t)NB*SS*3*DD];
__device__ __nv_bfloat16 g_outw3[(size_t)DD*3*DD];
__device__ __nv_bfloat16 g_chunk3[(size_t)NB*MAXC*3*DD];
__device__ __nv_bfloat16 g_pw1_3[(size_t)2*DD*3*DD];
__device__ __nv_bfloat16 g_hproc3[(size_t)NB*MAXC*3*2*DD];
__device__ __nv_bfloat16 g_pw2_3[(size_t)DD*3*2*DD];
// bf16 2-way split scratch (attention, 3-product path)
__device__ __nv_bfloat16 g_q2[(size_t)NB*NH*SS*2*HDIM];
__device__ __nv_bfloat16 g_k2[(size_t)NB*NH*SS*2*HDIM];
__device__ __nv_bfloat16 g_vT2[(size_t)NB*NH*HDIM*2*SS];
__device__ __nv_bfloat16 g_attn2[(size_t)NB*NH*SS*2*SS];

__device__ __forceinline__ float gelu_exact(float v) {
    return 0.5f * v * (1.0f + erff(v * 0.70710678118654752440f));
}
__device__ __forceinline__ uint32_t smem_u32(const void* p) {
    uint32_t a;
    asm("{ .reg .u64 t; cvta.to.shared.u64 t, %1; cvt.u32.u64 %0, t; }" : "=r"(a) : "l"(p));
    return a;
}

#define LDSM4(r0,r1,r2,r3,addr) \
    asm volatile("ldmatrix.sync.aligned.m8n8.x4.shared.b16 {%0,%1,%2,%3}, [%4];" \
        : "=r"(r0), "=r"(r1), "=r"(r2), "=r"(r3) : "r"(addr))

#define MMA16816(d, a, b0, b1) \
    asm volatile("mma.sync.aligned.m16n8k16.row.col.f32.bf16.bf16.f32 " \
        "{%0,%1,%2,%3},{%4,%5,%6,%7},{%8,%9},{%0,%1,%2,%3};" \
        : "+f"((d)[0]), "+f"((d)[1]), "+f"((d)[2]), "+f"((d)[3]) \
        : "r"((a)[0]), "r"((a)[1]), "r"((a)[2]), "r"((a)[3]), "r"(b0), "r"(b1))

#define CP_ASYNC16(dst, src, sz) \
    asm volatile("cp.async.ca.shared.global [%0], [%1], 16, %2;" :: "r"(dst), "l"(src), "r"(sz))
#define CP_COMMIT() asm volatile("cp.async.commit_group;" ::: "memory")
#define CP_WAIT1() asm volatile("cp.async.wait_group 1;" ::: "memory")
#define CP_WAIT0() asm volatile("cp.async.wait_group 0;" ::: "memory")

// ================= mma.sync bf16 split GEMM =================
// A2[M][ways*K] (hi|mid|lo along K), B2[N][ways*K]. C = sum of NP split products.
// Block 128x128, 8 warps (2x4), warp tile 64x32, K-chunk 64.
#define RSTRIDE 144
#define ATILE (128*RSTRIDE)        // 18432
#define BUFSZ (2*ATILE)            // 36864
#define TG_SMEM (2*BUFSZ)          // 73728

template<int NP, int ACT>
__global__ void __launch_bounds__(256)
tgemm_k(const __nv_bfloat16* __restrict__ A, const __nv_bfloat16* __restrict__ B,
        const float* __restrict__ bias, float* __restrict__ C,
        int M, int K, int lda, int ldb, int ldc,
        long long sAi, long long sAo, long long sBi, long long sBo,
        long long sCi, long long sCo, long long sbias, int innerN)
{
    const int segA_[6] = {0,0,1,0,1,2};
    const int segB_[6] = {0,1,0,2,1,0};
    extern __shared__ char smem[];
    uint32_t sb = smem_u32(smem);
    int tid = threadIdx.x;
    int z = blockIdx.z, zi = z % innerN, zo = z / innerN;
    A += (size_t)(zi*sAi + zo*sAo);
    B += (size_t)(zi*sBi + zo*sBo);
    C += (size_t)(zi*sCi + zo*sCo);
    int m0 = blockIdx.y * 128, n0 = blockIdx.x * 128;

    const int KPC = K >> 6;
    const int NC = NP * KPC;

    // ---- async chunk loader ----
    auto issue = [&](int kc, int buf) {
        int p = kc / KPC;
        int k0 = (kc - p * KPC) << 6;
        const __nv_bfloat16* Ap = A + (size_t)segA_[p] * K + k0;
        const __nv_bfloat16* Bp = B + (size_t)segB_[p] * K + k0;
        uint32_t sA = sb + buf * BUFSZ;
        uint32_t sB = sA + ATILE;
        #pragma unroll
        for (int i = 0; i < 4; i++) {
            int f = tid + (i << 8);
            int row = f >> 3, c = f & 7;
            int gr = m0 + row;
            int grc = gr < M ? gr : (M - 1);
            const void* src = Ap + (size_t)grc * lda + c * 8;
            uint32_t sz = gr < M ? 16u : 0u;
            CP_ASYNC16(sA + row * RSTRIDE + c * 16, src, sz);
        }
        #pragma unroll
        for (int i = 0; i < 4; i++) {
            int f = tid + (i << 8);
            int row = f >> 3, c = f & 7;
            const void* src = Bp + (size_t)(n0 + row) * ldb + c * 8;
            CP_ASYNC16(sB + row * RSTRIDE + c * 16, src, 16u);
        }
    };

    int lane = tid & 31, w = tid >> 5;
    int wm = w & 1, wn = w >> 1;
    uint32_t a_row = ((lane >> 3) & 1) * 8 + (lane & 7);
    uint32_t a_cs  = lane >> 4;
    uint32_t b_row = (lane >> 4) * 8 + (lane & 7);
    uint32_t b_cs  = (lane >> 3) & 1;

    float acc[4][4][4];
    #pragma unroll
    for (int i = 0; i < 4; i++)
        #pragma unroll
        for (int j = 0; j < 4; j++)
            #pragma unroll
            for (int r = 0; r < 4; r++) acc[i][j][r] = 0.f;

    issue(0, 0);
    CP_COMMIT();

    for (int kc = 0; kc < NC; kc++) {
        int cur = kc & 1;
        if (kc + 1 < NC) { issue(kc + 1, cur ^ 1); CP_COMMIT(); CP_WAIT1(); }
        else             { CP_WAIT0(); }
        __syncthreads();

        uint32_t sA = sb + cur * BUFSZ;
        uint32_t sB = sA + ATILE;
        #pragma unroll
        for (int ks = 0; ks < 4; ks++) {
            uint32_t av[4][4], bv[2][4];
            #pragma unroll
            for (int mt = 0; mt < 4; mt++) {
                uint32_t ad = sA + (wm*64 + mt*16 + a_row) * RSTRIDE + ((ks*2 + a_cs) << 4);
                LDSM4(av[mt][0], av[mt][1], av[mt][2], av[mt][3], ad);
            }
            #pragma unroll
            for (int bt = 0; bt < 2; bt++) {
                uint32_t bd = sB + (wn*32 + bt*16 + b_row) * RSTRIDE + ((ks*2 + b_cs) << 4);
                LDSM4(bv[bt][0], bv[bt][1], bv[bt][2], bv[bt][3], bd);
            }
            #pragma unroll
            for (int mt = 0; mt < 4; mt++)
                #pragma unroll
                for (int nt = 0; nt < 4; nt++) {
                    uint32_t b0 = bv[nt >> 1][(nt & 1) * 2];
                    uint32_t b1 = bv[nt >> 1][(nt & 1) * 2 + 1];
                    MMA16816(acc[mt][nt], av[mt], b0, b1);
                }
        }
        __syncthreads();
    }

    // ---- epilogue ----
    if (bias) bias += (size_t)z * (size_t)sbias;
    #pragma unroll
    for (int mt = 0; mt < 4; mt++) {
        int r0 = m0 + wm*64 + mt*16 + (lane >> 2);
        #pragma unroll
        for (int nt = 0; nt < 4; nt++) {
            int col = n0 + wn*32 + nt*8 + (lane & 3)*2;
            float bb0 = 0.f, bb1 = 0.f;
            if (bias) { bb0 = bias[col]; bb1 = bias[col+1]; }
            if (r0 < M) {
                float v0 = acc[mt][nt][0] + bb0;
                float v1 = acc[mt][nt][1] + bb1;
                if (ACT == 1) { v0 = gelu_exact(v0); v1 = gelu_exact(v1); }
                *(float2*)(C + (size_t)r0*ldc + col) = make_float2(v0, v1);
            }
            int r1 = r0 + 8;
            if (r1 < M) {
                float v0 = acc[mt][nt][2] + bb0;
                float v1 = acc[mt][nt][3] + bb1;
                if (ACT == 1) { v0 = gelu_exact(v0); v1 = gelu_exact(v1); }
                *(float2*)(C + (size_t)r1*ldc + col) = make_float2(v0, v1);
            }
        }
    }
}

// ================= split kernels =================
__global__ void split3_k(const float* __restrict__ src, __nv_bfloat16* __restrict__ dst,
                         long long total, int C) {
    long long idx = (long long)blockIdx.x * 256 + threadIdx.x;
    if (idx >= total) return;
    long long r = idx / C; int c = (int)(idx % C);
    float v = src[idx];
    __nv_bfloat16 h = __float2bfloat16_rn(v);
    float r1 = v - __bfloat162float(h);
    __nv_bfloat16 m = __float2bfloat16_rn(r1);
    __nv_bfloat16 l = __float2bfloat16_rn(r1 - __bfloat162float(m));
    __nv_bfloat16* d = dst + r * (3LL*C) + c;
    d[0] = h; d[C] = m; d[2*C] = l;
}

// bi3 gather: bi3[row=(b,s)][seg*3072 + kk] = x3[(b, s + (kk>=D))][seg*D + kk%D]
__global__ void bi3_k() {
    long long idx = (long long)blockIdx.x * 256 + threadIdx.x;   // uint4 units
    const long long total = (long long)ROWS_DET * (3*2*DD) / 8;
    if (idx >= total) return;
    int row = (int)(idx / (3*2*DD/8));
    int k8  = (int)(idx % (3*2*DD/8)) * 8;
    int seg = k8 / (2*DD);
    int kk  = k8 % (2*DD);
    int b = row / SM1, s = row % SM1;
    int srow = s + (kk >= DD ? 1 : 0);
    int scol = seg*DD + (kk >= DD ? kk - DD : kk);
    const uint4* src = (const uint4*)(g_x3 + ((size_t)(b*SS + srow))*(3*DD) + scol);
    ((uint4*)g_bi3)[idx] = *src;
}

__global__ void split2d_k(const float* __restrict__ src, __nv_bfloat16* __restrict__ dst,
                          long long total, int C) {
    long long idx = (long long)blockIdx.x * 256 + threadIdx.x;
    if (idx >= total) return;
    long long r = idx / C; int c = (int)(idx % C);
    float v = src[idx];
    __nv_bfloat16 hi = __float2bfloat16_rn(v);
    dst[r * (2LL*C) + c]     = hi;
    dst[r * (2LL*C) + C + c] = __float2bfloat16_rn(v - __bfloat162float(hi));
}

__global__ void split_qk_k() {
    long long idx = (long long)blockIdx.x * 256 + threadIdx.x;
    const long long total = (long long)NB*NH*SS*HDIM;
    if (idx >= total) return;
    int c = (int)(idx & 127);
    long long t = idx >> 7;
    int s = (int)(t & 1023);
    int z = (int)(t >> 10);
    int b = z / NH, h = z % NH;
    const float* base = g_qkv + ((size_t)(b*SS + s))*(3*DD) + h*HDIM + c;
    size_t o = ((size_t)z*SS + s) * (2*HDIM) + c;
    {
        float v = base[0];
        __nv_bfloat16 hi = __float2bfloat16_rn(v);
        g_q2[o] = hi; g_q2[o + HDIM] = __float2bfloat16_rn(v - __bfloat162float(hi));
    }
    {
        float v = base[DD];
        __nv_bfloat16 hi = __float2bfloat16_rn(v);
        g_k2[o] = hi; g_k2[o + HDIM] = __float2bfloat16_rn(v - __bfloat162float(hi));
    }
}

__global__ void split_vT_k() {
    long long idx = (long long)blockIdx.x * 256 + threadIdx.x;
    const long long total = (long long)NB*NH*HDIM*SS;
    if (idx >= total) return;
    int s = (int)(idx & 1023);
    long long t = idx >> 10;
    int c = (int)(t & 127);
    int z = (int)(t >> 7);
    int b = z / NH, h = z % NH;
    float v = g_qkv[((size_t)(b*SS + s))*(3*DD) + 2*DD + h*HDIM + c];
    __nv_bfloat16 hi = __float2bfloat16_rn(v);
    size_t o = ((size_t)z*HDIM + c) * (2*SS) + s;
    g_vT2[o] = hi;
    g_vT2[o + SS] = __float2bfloat16_rn(v - __bfloat162float(hi));
}

// ---------------- small kernels (unchanged numerics) ----------------
__global__ void norm_k() {
    int r = blockIdx.x;
    const float* p = g_xling + (size_t)r * DD;
    float ss = 0.f;
    for (int i = threadIdx.x; i < DD; i += 256) { float v = p[i]; ss += v*v; }
    __shared__ float sh[256];
    sh[threadIdx.x] = ss; __syncthreads();
    for (int o = 128; o > 0; o >>= 1) {
        if (threadIdx.x < o) sh[threadIdx.x] += sh[threadIdx.x + o];
        __syncthreads();
    }
    if (threadIdx.x == 0) g_norm[r] = fmaxf(sqrtf(sh[0]), 1e-8f);
}

__global__ void cos_k() {
    int b = blockIdx.y, t = blockIdx.x;
    int scale, i;
    if (t < 1023)      { scale = 1; i = t; }
    else if (t < 1534) { scale = 2; i = t - 1023; }
    else               { scale = 4; i = t - 1534; }
    int s0 = i * scale, s1 = s0 + scale;
    const float* a = g_xling + ((size_t)b*SS + s0) * DD;
    const float* c = g_xling + ((size_t)b*SS + s1) * DD;
    float d = 0.f;
    for (int j = threadIdx.x; j < DD; j += 256) d += a[j] * c[j];
    __shared__ float sh[256];
    sh[threadIdx.x] = d; __syncthreads();
    for (int o = 128; o > 0; o >>= 1) {
        if (threadIdx.x < o) sh[threadIdx.x] += sh[threadIdx.x + o];
        __syncthreads();
    }
    if (threadIdx.x == 0)
        g_cs[b*CS_TOT + t] = sh[0] / (g_norm[b*SS + s0] * g_norm[b*SS + s1]);
}

__global__ void base_k() {
    int idx = blockIdx.x * 256 + threadIdx.x;
    if (idx >= NB*SM1) return;
    int b = idx / SM1, j = idx % SM1;
    const int Ls[3]   = {1023, 511, 255};
    const int offs[3] = {0, 1023, 1534};
    float acc = 0.f;
    #pragma unroll
    for (int u = 0; u < 3; u++) {
        int L = Ls[u];
        float ratio = (float)((double)L / 1023.0);
        float src = ((float)j + 0.5f) * ratio - 0.5f;
        src = fminf(fmaxf(src, 0.0f), (float)(L - 1));
        int i0 = (int)floorf(src);
        int i1 = min(i0 + 1, L - 1);
        float w = src - (float)i0;
        const float* cs = g_cs + b*CS_TOT + offs[u];
        acc += cs[i0] * (1.0f - w) + cs[i1] * w;
    }
    g_base[idx] = 0.5f * (1.0f - acc / 3.0f);
}

__global__ void learned_final_k(const float* __restrict__ detW3,
                                const float* __restrict__ detb3) {
    int r = blockIdx.x;
    __shared__ float sh[256];
    __shared__ float sacc;
    if (threadIdx.x == 0) sacc = 0.f;
    for (int n = 0; n < 3; n++) {
        const float* h2p = g_h2 + ((size_t)n*ROWS_DET + r) * (DD/2);
        const float* w   = detW3 + n*(DD/2);
        float part = 0.f;
        for (int j = threadIdx.x; j < DD/2; j += 256) part += h2p[j] * w[j];
        __syncthreads();
        sh[threadIdx.x] = part; __syncthreads();
        for (int o = 128; o > 0; o >>= 1) {
            if (threadIdx.x < o) sh[threadIdx.x] += sh[threadIdx.x + o];
            __syncthreads();
        }
        if (threadIdx.x == 0) {
            float t = sh[0] + detb3[n];
            sacc += 1.0f / (1.0f + expf(-t));
        }
        __syncthreads();
    }
    if (threadIdx.x == 0)
        g_final[r] = 0.6f * g_base[r] + 0.4f * (sacc / 3.0f);
}

__global__ void seg_k() {
    int b = threadIdx.x;
    if (b >= NB) return;
    int cum = 0;
    for (int s = 0; s < SS; s++) {
        float bv = (s == 0) ? 1.0f : g_final[b*SM1 + s - 1];
        cum += (bv > 0.5f) ? 1 : 0;
        g_seg[b*SS + s] = cum - 1;
    }
    for (int m = 0; m < MAXC; m++) { g_segcount[b*MAXC+m] = 0; g_segstart[b*MAXC+m] = 0; }
    for (int s = 0; s < SS; s++) {
        int m = g_seg[b*SS + s];
        if (m < MAXC) {
            if (g_segcount[b*MAXC+m] == 0) g_segstart[b*MAXC+m] = s;
            g_segcount[b*MAXC+m]++;
        }
    }
}

__global__ void softmax_k() {
    int z = blockIdx.y, b = z / NH, q = blockIdx.x;
    float* row = g_scores + (size_t)z*SS*SS + (size_t)q*SS;
    int sq = g_seg[b*SS + q];
    const float scale = 1.0f / sqrtf(128.0f);
    __shared__ float sh[256];
    float mx = -3.402823e38f;
    for (int k = threadIdx.x; k < SS; k += 256) {
        float v = (g_seg[b*SS + k] == sq) ? row[k]*scale : -1e9f;
        mx = fmaxf(mx, v);
    }
    sh[threadIdx.x] = mx; __syncthreads();
    for (int o = 128; o > 0; o >>= 1) {
        if (threadIdx.x < o) sh[threadIdx.x] = fmaxf(sh[threadIdx.x], sh[threadIdx.x+o]);
        __syncthreads();
    }
    mx = sh[0]; __syncthreads();
    float sum = 0.f;
    for (int k = threadIdx.x; k < SS; k += 256) {
        float v = (g_seg[b*SS + k] == sq) ? row[k]*scale : -1e9f;
        float e = expf(v - mx);
        row[k] = e;
        sum += e;
    }
    sh[threadIdx.x] = sum; __syncthreads();
    for (int o = 128; o > 0; o >>= 1) {
        if (threadIdx.x < o) sh[threadIdx.x] += sh[threadIdx.x+o];
        __syncthreads();
    }
    float inv = 1.0f / sh[0];
    for (int k = threadIdx.x; k < SS; k += 256) row[k] *= inv;
}

__global__ void chunk_k(const float* __restrict__ size_emb,
                        const float* __restrict__ pos_enc) {
    int m = blockIdx.x, b = blockIdx.y;
    int cnt = g_segcount[b*MAXC + m];
    int st  = g_segstart[b*MAXC + m];
    for (int d = threadIdx.x; d < DD; d += 256) {
        float v;
        if (cnt > 0) {
            float sum = 0.f;
            for (int s = st; s < st + cnt; s++)
                sum += g_attnout[((size_t)b*SS + s)*DD + d];
            int cl = min(cnt, 1023);
            v = sum / (float)cnt + size_emb[(size_t)cl*DD + d];
        } else v = 0.f;
        v += pos_enc[(size_t)m*DD + d];
        g_chunk[((size_t)b*MAXC + m)*DD + d] = v;
    }
}

__global__ void ln_k(const float* __restrict__ gamma,
                     const float* __restrict__ beta,
                     float* __restrict__ out) {
    int r = blockIdx.x;
    const float* y = g_y + (size_t)r*DD;
    __shared__ float sh[256];
    float s = 0.f;
    for (int d = threadIdx.x; d < DD; d += 256) s += y[d];
    sh[threadIdx.x] = s; __syncthreads();
    for (int o = 128; o > 0; o >>= 1) {
        if (threadIdx.x < o) sh[threadIdx.x] += sh[threadIdx.x+o];
        __syncthreads();
    }
    float mu = sh[0] / (float)DD; __syncthreads();
    float v2 = 0.f;
    for (int d = threadIdx.x; d < DD; d += 256) { float t = y[d]-mu; v2 += t*t; }
    sh[threadIdx.x] = v2; __syncthreads();
    for (int o = 128; o > 0; o >>= 1) {
        if (threadIdx.x < o) sh[threadIdx.x] += sh[threadIdx.x+o];
        __syncthreads();
    }
    float inv = 1.0f / sqrtf(sh[0] / (float)DD + 1e-5f);
    for (int d = threadIdx.x; d < DD; d += 256)
        out[(size_t)r*DD + d] = (y[d] - mu) * inv * gamma[d] + beta[d];
}

// ---------------- host launchers ----------------
static void tgemm(int np, const __nv_bfloat16* A, const __nv_bfloat16* B, const float* bias,
                  float* C, int M, int N, int K, int lda, int ldb, int ldc, int act,
                  long long sAi, long long sAo, long long sBi, long long sBo,
                  long long sCi, long long sCo, long long sbias, int innerN, int batch)
{
    dim3 grid(N/128, (M + 127)/128, batch);
    if (np == 6) {
        if (act == 1) tgemm_k<6,1><<<grid,256,TG_SMEM>>>(A,B,bias,C,M,K,lda,ldb,ldc,sAi,sAo,sBi,sBo,sCi,sCo,sbias,innerN);
        else          tgemm_k<6,0><<<grid,256,TG_SMEM>>>(A,B,bias,C,M,K,lda,ldb,ldc,sAi,sAo,sBi,sBo,sCi,sCo,sbias,innerN);
    } else {
        if (act == 1) tgemm_k<3,1><<<grid,256,TG_SMEM>>>(A,B,bias,C,M,K,lda,ldb,ldc,sAi,sAo,sBi,sBo,sCi,sCo,sbias,innerN);
        else          tgemm_k<3,0><<<grid,256,TG_SMEM>>>(A,B,bias,C,M,K,lda,ldb,ldc,sAi,sAo,sBi,sBo,sCi,sCo,sbias,innerN);
    }
}

static void split3(const float* src, __nv_bfloat16* dst, long long rows, int cols) {
    long long total = rows * cols;
    split3_k<<<(unsigned)((total + 255)/256), 256>>>(src, dst, total, cols);
}

extern "C" void kernel_launch(void* const* d_in, const int* in_sizes, int n_in,
                              void* d_out, int out_size) {
    const float* x         = (const float*)d_in[0];
    const float* Wp        = (const float*)d_in[1];
    const float* bp        = (const float*)d_in[2];
    const float* detW1     = (const float*)d_in[3];
    const float* detb1     = (const float*)d_in[4];
    const float* detW2     = (const float*)d_in[5];
    const float* detb2     = (const float*)d_in[6];
    const float* detW3     = (const float*)d_in[7];
    const float* detb3     = (const float*)d_in[8];
    const float* in_proj_w = (const float*)d_in[9];
    const float* in_proj_b = (const float*)d_in[10];
    const float* out_w     = (const float*)d_in[11];
    const float* out_b     = (const float*)d_in[12];
    const float* size_emb  = (const float*)d_in[13];
    const float* pos_enc   = (const float*)d_in[14];
    const float* procW1    = (const float*)d_in[15];
    const float* procb1    = (const float*)d_in[16];
    const float* procW2    = (const float*)d_in[17];
    const float* procb2    = (const float*)d_in[18];
    const float* ln_g      = (const float*)d_in[19];
    const float* ln_b      = (const float*)d_in[20];
    float* outp = (float*)d_out;

    cudaFuncSetAttribute(tgemm_k<6,0>, cudaFuncAttributeMaxDynamicSharedMemorySize, TG_SMEM);
    cudaFuncSetAttribute(tgemm_k<6,1>, cudaFuncAttributeMaxDynamicSharedMemorySize, TG_SMEM);
    cudaFuncSetAttribute(tgemm_k<3,0>, cudaFuncAttributeMaxDynamicSharedMemorySize, TG_SMEM);
    cudaFuncSetAttribute(tgemm_k<3,1>, cudaFuncAttributeMaxDynamicSharedMemorySize, TG_SMEM);

    void *p;
    cudaGetSymbolAddress(&p, g_xling);   float* xling   = (float*)p;
    cudaGetSymbolAddress(&p, g_h1);      float* h1      = (float*)p;
    cudaGetSymbolAddress(&p, g_h2);      float* h2      = (float*)p;
    cudaGetSymbolAddress(&p, g_qkv);     float* qkv     = (float*)p;
    cudaGetSymbolAddress(&p, g_scores);  float* scores  = (float*)p;
    cudaGetSymbolAddress(&p, g_ctx);     float* ctx     = (float*)p;
    cudaGetSymbolAddress(&p, g_attnout); float* attnout = (float*)p;
    cudaGetSymbolAddress(&p, g_chunk);   float* chunk   = (float*)p;
    cudaGetSymbolAddress(&p, g_hproc);   float* hproc   = (float*)p;
    cudaGetSymbolAddress(&p, g_y);       float* yb      = (float*)p;
    cudaGetSymbolAddress(&p, g_x3);      __nv_bfloat16* x3      = (__nv_bfloat16*)p;
    cudaGetSymbolAddress(&p, g_Wp3);     __nv_bfloat16* Wp3     = (__nv_bfloat16*)p;
    cudaGetSymbolAddress(&p, g_bi3);     __nv_bfloat16* bi3     = (__nv_bfloat16*)p;
    cudaGetSymbolAddress(&p, g_detW1_3); __nv_bfloat16* dW1_3   = (__nv_bfloat16*)p;
    cudaGetSymbolAddress(&p, g_h1_3);    __nv_bfloat16* h1_3    = (__nv_bfloat16*)p;
    cudaGetSymbolAddress(&p, g_detW2_3); __nv_bfloat16* dW2_3   = (__nv_bfloat16*)p;
    cudaGetSymbolAddress(&p, g_wqkv3);   __nv_bfloat16* wqkv3   = (__nv_bfloat16*)p;
    cudaGetSymbolAddress(&p, g_ctx3);    __nv_bfloat16* ctx3    = (__nv_bfloat16*)p;
    cudaGetSymbolAddress(&p, g_outw3);   __nv_bfloat16* outw3   = (__nv_bfloat16*)p;
    cudaGetSymbolAddress(&p, g_chunk3);  __nv_bfloat16* chunk3  = (__nv_bfloat16*)p;
    cudaGetSymbolAddress(&p, g_pw1_3);   __nv_bfloat16* pw1_3   = (__nv_bfloat16*)p;
    cudaGetSymbolAddress(&p, g_hproc3);  __nv_bfloat16* hproc3  = (__nv_bfloat16*)p;
    cudaGetSymbolAddress(&p, g_pw2_3);   __nv_bfloat16* pw2_3   = (__nv_bfloat16*)p;
    cudaGetSymbolAddress(&p, g_q2);      __nv_bfloat16* q2      = (__nv_bfloat16*)p;
    cudaGetSymbolAddress(&p, g_k2);      __nv_bfloat16* k2      = (__nv_bfloat16*)p;
    cudaGetSymbolAddress(&p, g_vT2);     __nv_bfloat16* vT2     = (__nv_bfloat16*)p;
    cudaGetSymbolAddress(&p, g_attn2);   __nv_bfloat16* attn2   = (__nv_bfloat16*)p;
    cudaGetSymbolAddress(&p, g_scores);  // (already have scores)

    // ===== splits of inputs =====
    split3(x, x3, NB*SS, DD);
    split3(Wp, Wp3, DD, DD);
    split3(detW1, dW1_3, 3*DD, 2*DD);
    split3(detW2, dW2_3, 3*(DD/2), DD);
    split3(in_proj_w, wqkv3, 3*DD, DD);
    split3(out_w, outw3, DD, DD);
    split3(procW1, pw1_3, 2*DD, DD);
    split3(procW2, pw2_3, DD, 2*DD);
    {
        long long total8 = (long long)ROWS_DET * (3*2*DD) / 8;
        bi3_k<<<(unsigned)((total8 + 255)/256), 256>>>();
    }

    // ===== boundary path (6-product bf16 split ~ fp32 accuracy) =====
    // x_ling = x @ Wp^T + bp
    tgemm(6, x3, Wp3, bp, xling, NB*SS, DD, DD, 3*DD, 3*DD, DD, 0,
          0,0,0,0,0,0,0, 1, 1);
    norm_k<<<NB*SS, 256>>>();
    cos_k<<<dim3(CS_TOT, NB), 256>>>();
    base_k<<<(NB*SM1 + 255)/256, 256>>>();
    // h1 = gelu(bi @ detW1[n]^T + detb1[n])
    tgemm(6, bi3, dW1_3, detb1, h1, ROWS_DET, DD, 2*DD, 3*2*DD, 3*2*DD, DD, 1,
          0, 0, (long long)DD*3*2*DD, 0, (long long)ROWS_DET*DD, 0, DD, 3, 3);
    split3(h1, h1_3, (long long)3*ROWS_DET, DD);
    // h2 = gelu(h1 @ detW2[n]^T + detb2[n])
    tgemm(6, h1_3, dW2_3, detb2, h2, ROWS_DET, DD/2, DD, 3*DD, 3*DD, DD/2, 1,
          (long long)ROWS_DET*3*DD, 0, (long long)(DD/2)*3*DD, 0,
          (long long)ROWS_DET*(DD/2), 0, DD/2, 3, 3);
    learned_final_k<<<ROWS_DET, 256>>>(detW3, detb3);
    seg_k<<<1, NB>>>();

    // ===== continuous path (3-product bf16 split) =====
    // qkv = x @ in_proj_w^T + b
    tgemm(3, x3, wqkv3, in_proj_b, qkv, NB*SS, 3*DD, DD, 3*DD, 3*DD, 3*DD, 0,
          0,0,0,0,0,0,0, 1, 1);
    {
        long long t = (long long)NB*NH*SS*HDIM;
        split_qk_k<<<(unsigned)((t+255)/256), 256>>>();
        split_vT_k<<<(unsigned)((t+255)/256), 256>>>();
    }
    // scores[z] = q_z @ k_z^T
    tgemm(3, q2, k2, nullptr, scores, SS, SS, HDIM, 2*HDIM, 2*HDIM, SS, 0,
          (long long)SS*2*HDIM, (long long)NH*SS*2*HDIM,
          (long long)SS*2*HDIM, (long long)NH*SS*2*HDIM,
          (long long)SS*SS, (long long)NH*SS*SS, 0, NH, NB*NH);
    softmax_k<<<dim3(SS, NB*NH), 256>>>();
    {
        long long total = (long long)NB*NH*SS*SS;
        split2d_k<<<(unsigned)((total + 255)/256), 256>>>(scores, attn2, total, SS);
    }
    // ctx[z] = attn_z @ v_z (NT via vT2)
    tgemm(3, attn2, vT2, nullptr, ctx, SS, HDIM, SS, 2*SS, 2*SS, DD, 0,
          (long long)SS*2*SS, (long long)NH*SS*2*SS,
          (long long)HDIM*2*SS, (long long)NH*HDIM*2*SS,
          (long long)HDIM, (long long)SS*DD, 0, NH, NB*NH);
    // attn_out = ctx @ out_w^T + out_b
    split3(ctx, ctx3, NB*SS, DD);
    tgemm(3, ctx3, outw3, out_b, attnout, NB*SS, DD, DD, 3*DD, 3*DD, DD, 0,
          0,0,0,0,0,0,0, 1, 1);
    chunk_k<<<dim3(MAXC, NB), 256>>>(size_emb, pos_enc);
    // proc MLP
    split3(chunk, chunk3, NB*MAXC, DD);
    tgemm(3, chunk3, pw1_3, procb1, hproc, NB*MAXC, 2*DD, DD, 3*DD, 3*DD, 2*DD, 1,
          0,0,0,0,0,0,0, 1, 1);
    split3(hproc, hproc3, NB*MAXC, 2*DD);
    tgemm(3, hproc3, pw2_3, procb2, yb, NB*MAXC, DD, 2*DD, 3*2*DD, 3*2*DD, DD, 0,
          0,0,0,0,0,0,0, 1, 1);
    ln_k<<<NB*MAXC, 256>>>(ln_g, ln_b, outp);
}